// round 16
// baseline (speedup 1.0000x reference)
#include <cuda_runtime.h>

typedef unsigned long long ull;

#define OUT_KNN   2097152u
#define OUT_LOCAL 35651584u
#define CAP 96

__device__ int   g_idx[8 * 2048 * 16];
__device__ float g_h[16384 * 128];
__device__ float g_z[16384 * 128];
__device__ float g_w1t[64 * 128];     // [c][o]
__device__ float g_w2t[128 * 128];    // [c][o]

// Distance matching the reference lowering (proven exact in R7):
//   sq  = (x*x + y*y) + z*z
//   dot = fma(z,z', fma(y,y', x*x'))
//   d2  = (sq_i + sq_j) - 2*dot
__device__ __forceinline__ float d2_of(float4 a, float4 b) {
    float dot = __fmaf_rn(a.z, b.z, __fmaf_rn(a.y, b.y, __fmul_rn(a.x, b.x)));
    return __fsub_rn(__fadd_rn(a.w, b.w), __fmul_rn(2.0f, dot));
}

__device__ __forceinline__ ull fma2(ull a, ull b, ull c) {
    ull d;
    asm("fma.rn.f32x2 %0,%1,%2,%3;" : "=l"(d) : "l"(a), "l"(b), "l"(c));
    return d;
}
__device__ __forceinline__ ull dupf(float a) {
    ull r;
    asm("mov.b64 %0,{%1,%1};" : "=l"(r) : "f"(a));
    return r;
}

// ---------------------------------------------------------------------------
// K0: one-time weight transposes into [c][o] layout.
// ---------------------------------------------------------------------------
__global__ __launch_bounds__(256) void transpose_kernel(const float* __restrict__ w1,
                                                        const float* __restrict__ w2)
{
    int e = blockIdx.x * 256 + threadIdx.x;          // grid covers 16384
    if (e < 8192) {
        int o = e >> 6, c = e & 63;
        g_w1t[c * 128 + o] = w1[e];
    }
    int o2 = e >> 7, c2 = e & 127;
    g_w2t[c2 * 128 + o2] = w2[e];
}

// ---------------------------------------------------------------------------
// K1 v6: exact top-16 KNN with a SHARED per-query threshold.
//   Block = 256 thr = 32 queries x 8 j-eighths (h = warp id, warp-uniform).
//   Pass A: per-eighth T_h = max of 16 chunk-minima (chunk=16); then
//           T = min_h T_h  (valid: every T_h >= global 16th smallest).
//   Pass B: append j with d2 <= T to per-query smem list (atomic, ~30/query).
//   Select: ONE thread per query (warp 0) runs the single-copy unroll-1
//           lexicographic (d2, j) insert network over the candidate set.
//           Set-based + order-independent network => deterministic, exact,
//           jax.lax.top_k tie-stable. Overflow (>CAP) falls back to an exact
//           full-2048 scan through the SAME loop (no second network copy).
//   Writes g_idx + local_coords. Selection provably identical to R13/R15.
// ---------------------------------------------------------------------------
__global__ __launch_bounds__(256) void knn_kernel(const float* __restrict__ coords,
                                                  float* __restrict__ out)
{
    __shared__ float4 cs[2048];                      // 32 KB
    __shared__ float  tmin[8][32];                   // 1 KB
    __shared__ int    qcnt[32];
    __shared__ unsigned short qbuf[32][CAP];         // 6 KB

    const int t = threadIdx.x, q = t & 31, h = t >> 5;   // h = warp id
    const int b = blockIdx.y;
    const int i = blockIdx.x * 32 + q;
    const float* cb = coords + (size_t)b * 3 * 2048;

    if (t < 32) qcnt[t] = 0;
    for (int j = t; j < 2048; j += 256) {
        float X = cb[j], Y = cb[2048 + j], Z = cb[4096 + j];
        float s = __fadd_rn(__fadd_rn(__fmul_rn(X, X), __fmul_rn(Y, Y)), __fmul_rn(Z, Z));
        cs[j] = make_float4(X, Y, Z, s);
    }
    __syncthreads();

    const float4 ci = cs[i];
    const float INF = __int_as_float(0x7f800000);
    const int jbeg = h << 8;                          // 256 per eighth

    // Pass A: per-eighth threshold (broadcast LDS, 4 independent min chains)
    float T = -INF;
#pragma unroll 1
    for (int ch = 0; ch < 16; ch++) {
        const float4* p = cs + jbeg + ch * 16;
        float m0 = INF, m1 = INF, m2 = INF, m3 = INF;
#pragma unroll
        for (int u = 0; u < 16; u += 4) {
            m0 = fminf(m0, d2_of(ci, p[u]));
            m1 = fminf(m1, d2_of(ci, p[u + 1]));
            m2 = fminf(m2, d2_of(ci, p[u + 2]));
            m3 = fminf(m3, d2_of(ci, p[u + 3]));
        }
        T = fmaxf(T, fminf(fminf(m0, m1), fminf(m2, m3)));
    }
    tmin[h][q] = T;
    __syncthreads();

    float Tq = tmin[0][q];
#pragma unroll
    for (int s = 1; s < 8; s++) Tq = fminf(Tq, tmin[s][q]);

    // Pass B: append candidates (expected ~4 per thread, ~30 per query).
#pragma unroll 4
    for (int u = 0; u < 256; u++) {
        int j = jbeg + u;
        float d2 = d2_of(ci, cs[j]);
        if (d2 <= Tq) {
            int pos = atomicAdd(&qcnt[q], 1);
            if (pos < CAP) qbuf[q][pos] = (unsigned short)j;
        }
    }
    __syncthreads();
    if (h) return;

    // Selection: one thread per query, single insert-network copy.
    const int cnt = qcnt[q];
    const bool ovf = cnt > CAP;
    const int n_it = ovf ? 2048 : cnt;

    float dd[16]; int nb[16];
#pragma unroll
    for (int s = 0; s < 16; s++) { dd[s] = INF; nb[s] = 0x7fffffff; }

#pragma unroll 1
    for (int e = 0; e < n_it; e++) {
        int j = ovf ? e : (int)qbuf[q][e];
        float de = d2_of(ci, cs[j]);
        if (de <= Tq && (de < dd[15] || (de == dd[15] && j < nb[15]))) {
            float cd = de; int cj = j;
#pragma unroll
            for (int s = 0; s < 16; s++) {
                bool lt = (cd < dd[s]) || (cd == dd[s] && cj < nb[s]);
                float nd = lt ? cd : dd[s];
                int   ni = lt ? cj : nb[s];
                cd = lt ? dd[s] : cd; cj = lt ? nb[s] : cj;
                dd[s] = nd; nb[s] = ni;
            }
        }
    }

    int* ip = &g_idx[(size_t)(b * 2048 + i) * 16];
#pragma unroll
    for (int s = 0; s < 16; s++) ip[s] = nb[s];

#pragma unroll
    for (int d = 0; d < 3; d++) {
        float cv = d == 0 ? ci.x : (d == 1 ? ci.y : ci.z);
        float* L = out + OUT_LOCAL + ((size_t)(b * 3 + d) * 2048 + i) * 16;
#pragma unroll
        for (int s = 0; s < 16; s++) {
            float4 cn = cs[nb[s]];
            float nv = d == 0 ? cn.x : (d == 1 ? cn.y : cn.z);
            L[s] = __fsub_rn(cv, nv);
        }
    }
}

// ---------------------------------------------------------------------------
// K2a/K2b: per-point MLP (unchanged from R13; l2 measured 27us, l1 ~13us).
// ---------------------------------------------------------------------------
__global__ __launch_bounds__(256) void layer1_kernel(const float* __restrict__ x,
                                                     const float* __restrict__ g1,
                                                     const float* __restrict__ b1,
                                                     const float* __restrict__ m1,
                                                     const float* __restrict__ v1)
{
    __shared__ float xs[64 * 66];            // [c][p], stride 66
    const int t = threadIdx.x, l = t & 31, wg = t >> 5;
    const int pblk = blockIdx.x >> 1, half = blockIdx.x & 1;
    const int P0 = pblk * 64;
    const int b = P0 >> 11, p0 = P0 & 2047;
    const float* xb = x + (size_t)b * 64 * 2048 + p0;

    for (int e = t; e < 4096; e += 256) {
        int c = e >> 6, p = e & 63;
        xs[c * 66 + p] = xb[c * 2048 + p];
    }
    const int o0 = half * 64 + l * 2;
    float iv0 = g1[o0] / sqrtf(v1[o0] + 1e-5f);
    float cc0 = b1[o0] - m1[o0] * iv0;
    float iv1 = g1[o0 + 1] / sqrtf(v1[o0 + 1] + 1e-5f);
    float cc1 = b1[o0 + 1] - m1[o0 + 1] * iv1;
    __syncthreads();

    ull acc[8];
#pragma unroll
    for (int s = 0; s < 8; s++) acc[s] = 0;

    const float* wbase = g_w1t + o0;
    float2 wv = *(const float2*)(wbase);
#pragma unroll 4
    for (int c = 0; c < 64; c++) {
        float2 wc = wv;
        if (c < 63) wv = *(const float2*)(wbase + (c + 1) * 128);
        ull w0 = dupf(wc.x), w1d = dupf(wc.y);
        const ull* xp = (const ull*)(xs + c * 66 + wg * 8);
        ull x0 = xp[0], x1 = xp[1], x2 = xp[2], x3 = xp[3];
        acc[0] = fma2(w0, x0, acc[0]);  acc[1] = fma2(w0, x1, acc[1]);
        acc[2] = fma2(w0, x2, acc[2]);  acc[3] = fma2(w0, x3, acc[3]);
        acc[4] = fma2(w1d, x0, acc[4]); acc[5] = fma2(w1d, x1, acc[5]);
        acc[6] = fma2(w1d, x2, acc[6]); acc[7] = fma2(w1d, x3, acc[7]);
    }

    float* zb = g_h + ((size_t)P0 + wg * 8) * 128 + o0;
#pragma unroll
    for (int pp = 0; pp < 4; pp++) {
        float s0 = __uint_as_float((unsigned)acc[pp]);
        float s1 = __uint_as_float((unsigned)acc[4 + pp]);
        float2 v0 = make_float2(fmaxf(s0 * iv0 + cc0, 0.f), fmaxf(s1 * iv1 + cc1, 0.f));
        float t0 = __uint_as_float((unsigned)(acc[pp] >> 32));
        float t1 = __uint_as_float((unsigned)(acc[4 + pp] >> 32));
        float2 v1v = make_float2(fmaxf(t0 * iv0 + cc0, 0.f), fmaxf(t1 * iv1 + cc1, 0.f));
        *(float2*)(zb + (size_t)(2 * pp) * 128)     = v0;
        *(float2*)(zb + (size_t)(2 * pp + 1) * 128) = v1v;
    }
}

__global__ __launch_bounds__(256) void layer2_kernel(const float* __restrict__ g2,
                                                     const float* __restrict__ b2,
                                                     const float* __restrict__ m2,
                                                     const float* __restrict__ v2)
{
    __shared__ float xs[128 * 66];           // [c][p], stride 66
    const int t = threadIdx.x, l = t & 31, wg = t >> 5;
    const int pblk = blockIdx.x >> 1, half = blockIdx.x & 1;
    const int P0 = pblk * 64;
    const float* hb = g_h + (size_t)P0 * 128;

    for (int e = t; e < 8192; e += 256) {
        int p = e >> 7, c = e & 127;
        xs[c * 66 + p] = hb[e];
    }
    const int o0 = half * 64 + l * 2;
    float iv0 = g2[o0] / sqrtf(v2[o0] + 1e-5f);
    float cc0 = b2[o0] - m2[o0] * iv0;
    float iv1 = g2[o0 + 1] / sqrtf(v2[o0 + 1] + 1e-5f);
    float cc1 = b2[o0 + 1] - m2[o0 + 1] * iv1;
    __syncthreads();

    ull acc[8];
#pragma unroll
    for (int s = 0; s < 8; s++) acc[s] = 0;

    const float* wbase = g_w2t + o0;
    float2 wv = *(const float2*)(wbase);
#pragma unroll 4
    for (int c = 0; c < 128; c++) {
        float2 wc = wv;
        if (c < 127) wv = *(const float2*)(wbase + (c + 1) * 128);
        ull w0 = dupf(wc.x), w1d = dupf(wc.y);
        const ull* xp = (const ull*)(xs + c * 66 + wg * 8);
        ull x0 = xp[0], x1 = xp[1], x2 = xp[2], x3 = xp[3];
        acc[0] = fma2(w0, x0, acc[0]);  acc[1] = fma2(w0, x1, acc[1]);
        acc[2] = fma2(w0, x2, acc[2]);  acc[3] = fma2(w0, x3, acc[3]);
        acc[4] = fma2(w1d, x0, acc[4]); acc[5] = fma2(w1d, x1, acc[5]);
        acc[6] = fma2(w1d, x2, acc[6]); acc[7] = fma2(w1d, x3, acc[7]);
    }

    float* zb = g_z + ((size_t)P0 + wg * 8) * 128 + o0;
#pragma unroll
    for (int pp = 0; pp < 4; pp++) {
        float s0 = __uint_as_float((unsigned)acc[pp]);
        float s1 = __uint_as_float((unsigned)acc[4 + pp]);
        float2 v0 = make_float2(fmaxf(s0 * iv0 + cc0, 0.f), fmaxf(s1 * iv1 + cc1, 0.f));
        float t0 = __uint_as_float((unsigned)(acc[pp] >> 32));
        float t1 = __uint_as_float((unsigned)(acc[4 + pp] >> 32));
        float2 v1v = make_float2(fmaxf(t0 * iv0 + cc0, 0.f), fmaxf(t1 * iv1 + cc1, 0.f));
        *(float2*)(zb + (size_t)(2 * pp) * 128)     = v0;
        *(float2*)(zb + (size_t)(2 * pp + 1) * 128) = v1v;
    }
}

// ---------------------------------------------------------------------------
// K3: gather (unchanged). Warp = 2 queries; 4 channel-chunks of 32 via smem;
// y via REDUX.UMAX (z >= +0 post-ReLU => fp max == uint max).
// ---------------------------------------------------------------------------
__global__ __launch_bounds__(128) void gather_kernel(float* __restrict__ out)
{
    __shared__ float S[4][32 * 33];
    const int t = threadIdx.x, w = t >> 5, l = t & 31;
    const int Q0 = blockIdx.x * 8 + w * 2;
    const int qg = Q0 + (l >> 4);
    const int b = qg >> 11, i = qg & 2047, k = l & 15;
    const int i0 = Q0 & 2047;

    const int jl = g_idx[qg * 16 + k];
    const int gr = (b << 11) + jl;
    float* Sw = S[w];
    const unsigned gmask = (l < 16) ? 0x0000FFFFu : 0xFFFF0000u;

    for (int ch = 0; ch < 4; ch++) {
#pragma unroll 8
        for (int r = 0; r < 32; r++) {
            int row = __shfl_sync(0xffffffffu, gr, r);
            Sw[r * 33 + l] = g_z[(size_t)row * 128 + ch * 32 + l];
        }
        __syncwarp();
        float* ob = out + OUT_KNN + ((size_t)(b * 128 + ch * 32) * 2048 + i0) * 16 + l;
        float* yb = out + (size_t)(b * 128 + ch * 32) * 2048 + i;
#pragma unroll 8
        for (int oo = 0; oo < 32; oo++) {
            float v = Sw[l * 33 + oo];
            unsigned mv = __reduce_max_sync(gmask, __float_as_uint(v));
            ob[(size_t)oo * 32768] = v;
            if (k == 0) yb[oo * 2048] = __uint_as_float(mv);
        }
        __syncwarp();
    }
}

extern "C" void kernel_launch(void* const* d_in, const int* in_sizes, int n_in,
                              void* d_out, int out_size)
{
    const float* x      = (const float*)d_in[0];
    const float* coords = (const float*)d_in[1];
    const float* w1     = (const float*)d_in[2];
    const float* g1     = (const float*)d_in[3];
    const float* b1     = (const float*)d_in[4];
    const float* m1     = (const float*)d_in[5];
    const float* v1     = (const float*)d_in[6];
    const float* w2     = (const float*)d_in[7];
    const float* g2     = (const float*)d_in[8];
    const float* b2     = (const float*)d_in[9];
    const float* m2     = (const float*)d_in[10];
    const float* v2     = (const float*)d_in[11];
    float* out = (float*)d_out;

    // knn kept at launch index 3 (the slot ncu captures).
    transpose_kernel<<<64, 256>>>(w1, w2);
    layer1_kernel<<<512, 256>>>(x, g1, b1, m1, v1);
    layer2_kernel<<<512, 256>>>(g2, b2, m2, v2);
    knn_kernel<<<dim3(64, 8), 256>>>(coords, out);
    gather_kernel<<<2048, 128>>>(out);
}

// round 17
// speedup vs baseline: 8.7827x; 8.7827x over previous
#include <cuda_runtime.h>

typedef unsigned long long ull;

#define OUT_KNN   2097152u
#define OUT_LOCAL 35651584u
#define CAP 96

__device__ int   g_idx[8 * 2048 * 16];
__device__ float g_h[16384 * 128];
__device__ float g_z[16384 * 128];
__device__ float g_w1t[64 * 128];     // [c][o]
__device__ float g_w2t[128 * 128];    // [c][o]

// Distance matching the reference lowering (proven exact in R7):
//   sq  = (x*x + y*y) + z*z
//   dot = fma(z,z', fma(y,y', x*x'))
//   d2  = (sq_i + sq_j) - 2*dot
__device__ __forceinline__ float d2_of(float4 a, float4 b) {
    float dot = __fmaf_rn(a.z, b.z, __fmaf_rn(a.y, b.y, __fmul_rn(a.x, b.x)));
    return __fsub_rn(__fadd_rn(a.w, b.w), __fmul_rn(2.0f, dot));
}

__device__ __forceinline__ ull fma2(ull a, ull b, ull c) {
    ull d;
    asm("fma.rn.f32x2 %0,%1,%2,%3;" : "=l"(d) : "l"(a), "l"(b), "l"(c));
    return d;
}
__device__ __forceinline__ ull dupf(float a) {
    ull r;
    asm("mov.b64 %0,{%1,%1};" : "=l"(r) : "f"(a));
    return r;
}

// ---------------------------------------------------------------------------
// K0: one-time weight transposes into [c][o] layout.
// ---------------------------------------------------------------------------
__global__ __launch_bounds__(256) void transpose_kernel(const float* __restrict__ w1,
                                                        const float* __restrict__ w2)
{
    int e = blockIdx.x * 256 + threadIdx.x;          // grid covers 16384
    if (e < 8192) {
        int o = e >> 6, c = e & 63;
        g_w1t[c * 128 + o] = w1[e];
    }
    int o2 = e >> 7, c2 = e & 127;
    g_w2t[c2 * 128 + o2] = w2[e];
}

// ---------------------------------------------------------------------------
// K1 v7: exact top-16 KNN with a TIGHT shared per-query threshold.
//   Block = 256 thr = 32 queries x 8 j-eighths (h = warp id, warp-uniform).
//   Pass A: each (h,q) computes 16 chunk-minima (chunk=16) -> smem [c][h][q].
//   Tq = 16th smallest of the 128 chunk-minima. VALID: the minima are 128
//        distinct actual elements, so their 16th smallest >= global 16th
//        smallest; all true top-16 pass d2 <= Tq; and the 16 smallest minima
//        themselves guarantee cnt >= 16. TIGHT: Tq ~ global rank 20-35, so
//        cnt ~ 25-45 << CAP (R16's min-of-maxes sat at rank ~240 -> overflow).
//   Pass B: append j with d2 <= Tq to per-query smem list (atomic).
//   Select: warp 0, one lane per query, single-copy unroll-1 lexicographic
//           (d2, j) insert network over the candidate set. Set-based and
//           order-independent => deterministic, exact, top_k tie-stable.
//           Overflow (>CAP) falls back to exact full-2048 scan (same loop).
//   smem: cs 32KB + 16KB pool (minima, then reused as qcnt/tq/qbuf) = 48KB.
// ---------------------------------------------------------------------------
__global__ __launch_bounds__(256) void knn_kernel(const float* __restrict__ coords,
                                                  float* __restrict__ out)
{
    __shared__ float4 cs[2048];                      // 32 KB
    __shared__ char   pool[16384];                   // 16 KB (phase-overlapped)
    float*          vmin = (float*)pool;             // phase 1: [16][8][32]
    int*            qcnt = (int*)pool;               // phase 2: [32]
    float*          tqs  = (float*)(pool + 128);     // phase 2: [32]
    unsigned short* qbuf = (unsigned short*)(pool + 256);  // phase 2: [32][CAP]

    const int t = threadIdx.x, q = t & 31, h = t >> 5;   // h = warp id
    const int b = blockIdx.y;
    const int i = blockIdx.x * 32 + q;
    const float* cb = coords + (size_t)b * 3 * 2048;

    for (int j = t; j < 2048; j += 256) {
        float X = cb[j], Y = cb[2048 + j], Z = cb[4096 + j];
        float s = __fadd_rn(__fadd_rn(__fmul_rn(X, X), __fmul_rn(Y, Y)), __fmul_rn(Z, Z));
        cs[j] = make_float4(X, Y, Z, s);
    }
    __syncthreads();

    const float4 ci = cs[i];
    const float INF = __int_as_float(0x7f800000);
    const int jbeg = h << 8;                          // 256 per eighth

    // Pass A: 16 chunk-minima (chunk=16) -> vmin[(ch*8+h)*32+q] (bank-clean)
#pragma unroll 1
    for (int ch = 0; ch < 16; ch++) {
        const float4* p = cs + jbeg + ch * 16;
        float m0 = INF, m1 = INF, m2 = INF, m3 = INF;
#pragma unroll
        for (int u = 0; u < 16; u += 4) {
            m0 = fminf(m0, d2_of(ci, p[u]));
            m1 = fminf(m1, d2_of(ci, p[u + 1]));
            m2 = fminf(m2, d2_of(ci, p[u + 2]));
            m3 = fminf(m3, d2_of(ci, p[u + 3]));
        }
        vmin[(ch * 8 + h) * 32 + q] = fminf(fminf(m0, m1), fminf(m2, m3));
    }
    __syncthreads();

    // Threshold: warp 0, lane q: Tq = 16th smallest of this query's 128 minima.
    float Tq_reg = INF;
    if (h == 0) {
        float vv[16];
#pragma unroll
        for (int s = 0; s < 16; s++) vv[s] = INF;
#pragma unroll 1
        for (int e = 0; e < 128; e++) {
            float d = vmin[e * 32 + q];
            if (d < vv[15]) {
                float c = d;
#pragma unroll
                for (int s = 0; s < 16; s++) {
                    float lo = fminf(c, vv[s]);
                    c = fmaxf(c, vv[s]);
                    vv[s] = lo;
                }
            }
        }
        Tq_reg = vv[15];
    }
    __syncthreads();                                  // vmin reads complete
    if (h == 0) { tqs[q] = Tq_reg; qcnt[q] = 0; }     // pool reuse begins
    __syncthreads();
    const float Tq = tqs[q];

    // Pass B: append candidates (cnt in [16, ~45] expected).
#pragma unroll 4
    for (int u = 0; u < 256; u++) {
        int j = jbeg + u;
        float d2 = d2_of(ci, cs[j]);
        if (d2 <= Tq) {
            int pos = atomicAdd(&qcnt[q], 1);
            if (pos < CAP) qbuf[q * CAP + pos] = (unsigned short)j;
        }
    }
    __syncthreads();
    if (h) return;

    // Selection: one lane per query, single insert-network copy.
    const int cnt = qcnt[q];
    const bool ovf = cnt > CAP;
    const int n_it = ovf ? 2048 : cnt;

    float dd[16]; int nb[16];
#pragma unroll
    for (int s = 0; s < 16; s++) { dd[s] = INF; nb[s] = 0x7fffffff; }

#pragma unroll 1
    for (int e = 0; e < n_it; e++) {
        int j = ovf ? e : (int)qbuf[q * CAP + e];
        float de = d2_of(ci, cs[j]);
        if (de <= Tq && (de < dd[15] || (de == dd[15] && j < nb[15]))) {
            float cd = de; int cj = j;
#pragma unroll
            for (int s = 0; s < 16; s++) {
                bool lt = (cd < dd[s]) || (cd == dd[s] && cj < nb[s]);
                float nd = lt ? cd : dd[s];
                int   ni = lt ? cj : nb[s];
                cd = lt ? dd[s] : cd; cj = lt ? nb[s] : cj;
                dd[s] = nd; nb[s] = ni;
            }
        }
    }

    int* ip = &g_idx[(size_t)(b * 2048 + i) * 16];
#pragma unroll
    for (int s = 0; s < 16; s++) ip[s] = nb[s];

#pragma unroll
    for (int d = 0; d < 3; d++) {
        float cv = d == 0 ? ci.x : (d == 1 ? ci.y : ci.z);
        float* L = out + OUT_LOCAL + ((size_t)(b * 3 + d) * 2048 + i) * 16;
#pragma unroll
        for (int s = 0; s < 16; s++) {
            float4 cn = cs[nb[s]];
            float nv = d == 0 ? cn.x : (d == 1 ? cn.y : cn.z);
            L[s] = __fsub_rn(cv, nv);
        }
    }
}

// ---------------------------------------------------------------------------
// K2a/K2b: per-point MLP (unchanged; l2 measured 27us, l1 ~13us).
// ---------------------------------------------------------------------------
__global__ __launch_bounds__(256) void layer1_kernel(const float* __restrict__ x,
                                                     const float* __restrict__ g1,
                                                     const float* __restrict__ b1,
                                                     const float* __restrict__ m1,
                                                     const float* __restrict__ v1)
{
    __shared__ float xs[64 * 66];            // [c][p], stride 66
    const int t = threadIdx.x, l = t & 31, wg = t >> 5;
    const int pblk = blockIdx.x >> 1, half = blockIdx.x & 1;
    const int P0 = pblk * 64;
    const int b = P0 >> 11, p0 = P0 & 2047;
    const float* xb = x + (size_t)b * 64 * 2048 + p0;

    for (int e = t; e < 4096; e += 256) {
        int c = e >> 6, p = e & 63;
        xs[c * 66 + p] = xb[c * 2048 + p];
    }
    const int o0 = half * 64 + l * 2;
    float iv0 = g1[o0] / sqrtf(v1[o0] + 1e-5f);
    float cc0 = b1[o0] - m1[o0] * iv0;
    float iv1 = g1[o0 + 1] / sqrtf(v1[o0 + 1] + 1e-5f);
    float cc1 = b1[o0 + 1] - m1[o0 + 1] * iv1;
    __syncthreads();

    ull acc[8];
#pragma unroll
    for (int s = 0; s < 8; s++) acc[s] = 0;

    const float* wbase = g_w1t + o0;
    float2 wv = *(const float2*)(wbase);
#pragma unroll 4
    for (int c = 0; c < 64; c++) {
        float2 wc = wv;
        if (c < 63) wv = *(const float2*)(wbase + (c + 1) * 128);
        ull w0 = dupf(wc.x), w1d = dupf(wc.y);
        const ull* xp = (const ull*)(xs + c * 66 + wg * 8);
        ull x0 = xp[0], x1 = xp[1], x2 = xp[2], x3 = xp[3];
        acc[0] = fma2(w0, x0, acc[0]);  acc[1] = fma2(w0, x1, acc[1]);
        acc[2] = fma2(w0, x2, acc[2]);  acc[3] = fma2(w0, x3, acc[3]);
        acc[4] = fma2(w1d, x0, acc[4]); acc[5] = fma2(w1d, x1, acc[5]);
        acc[6] = fma2(w1d, x2, acc[6]); acc[7] = fma2(w1d, x3, acc[7]);
    }

    float* zb = g_h + ((size_t)P0 + wg * 8) * 128 + o0;
#pragma unroll
    for (int pp = 0; pp < 4; pp++) {
        float s0 = __uint_as_float((unsigned)acc[pp]);
        float s1 = __uint_as_float((unsigned)acc[4 + pp]);
        float2 v0 = make_float2(fmaxf(s0 * iv0 + cc0, 0.f), fmaxf(s1 * iv1 + cc1, 0.f));
        float t0 = __uint_as_float((unsigned)(acc[pp] >> 32));
        float t1 = __uint_as_float((unsigned)(acc[4 + pp] >> 32));
        float2 v1v = make_float2(fmaxf(t0 * iv0 + cc0, 0.f), fmaxf(t1 * iv1 + cc1, 0.f));
        *(float2*)(zb + (size_t)(2 * pp) * 128)     = v0;
        *(float2*)(zb + (size_t)(2 * pp + 1) * 128) = v1v;
    }
}

__global__ __launch_bounds__(256) void layer2_kernel(const float* __restrict__ g2,
                                                     const float* __restrict__ b2,
                                                     const float* __restrict__ m2,
                                                     const float* __restrict__ v2)
{
    __shared__ float xs[128 * 66];           // [c][p], stride 66
    const int t = threadIdx.x, l = t & 31, wg = t >> 5;
    const int pblk = blockIdx.x >> 1, half = blockIdx.x & 1;
    const int P0 = pblk * 64;
    const float* hb = g_h + (size_t)P0 * 128;

    for (int e = t; e < 8192; e += 256) {
        int p = e >> 7, c = e & 127;
        xs[c * 66 + p] = hb[e];
    }
    const int o0 = half * 64 + l * 2;
    float iv0 = g2[o0] / sqrtf(v2[o0] + 1e-5f);
    float cc0 = b2[o0] - m2[o0] * iv0;
    float iv1 = g2[o0 + 1] / sqrtf(v2[o0 + 1] + 1e-5f);
    float cc1 = b2[o0 + 1] - m2[o0 + 1] * iv1;
    __syncthreads();

    ull acc[8];
#pragma unroll
    for (int s = 0; s < 8; s++) acc[s] = 0;

    const float* wbase = g_w2t + o0;
    float2 wv = *(const float2*)(wbase);
#pragma unroll 4
    for (int c = 0; c < 128; c++) {
        float2 wc = wv;
        if (c < 127) wv = *(const float2*)(wbase + (c + 1) * 128);
        ull w0 = dupf(wc.x), w1d = dupf(wc.y);
        const ull* xp = (const ull*)(xs + c * 66 + wg * 8);
        ull x0 = xp[0], x1 = xp[1], x2 = xp[2], x3 = xp[3];
        acc[0] = fma2(w0, x0, acc[0]);  acc[1] = fma2(w0, x1, acc[1]);
        acc[2] = fma2(w0, x2, acc[2]);  acc[3] = fma2(w0, x3, acc[3]);
        acc[4] = fma2(w1d, x0, acc[4]); acc[5] = fma2(w1d, x1, acc[5]);
        acc[6] = fma2(w1d, x2, acc[6]); acc[7] = fma2(w1d, x3, acc[7]);
    }

    float* zb = g_z + ((size_t)P0 + wg * 8) * 128 + o0;
#pragma unroll
    for (int pp = 0; pp < 4; pp++) {
        float s0 = __uint_as_float((unsigned)acc[pp]);
        float s1 = __uint_as_float((unsigned)acc[4 + pp]);
        float2 v0 = make_float2(fmaxf(s0 * iv0 + cc0, 0.f), fmaxf(s1 * iv1 + cc1, 0.f));
        float t0 = __uint_as_float((unsigned)(acc[pp] >> 32));
        float t1 = __uint_as_float((unsigned)(acc[4 + pp] >> 32));
        float2 v1v = make_float2(fmaxf(t0 * iv0 + cc0, 0.f), fmaxf(t1 * iv1 + cc1, 0.f));
        *(float2*)(zb + (size_t)(2 * pp) * 128)     = v0;
        *(float2*)(zb + (size_t)(2 * pp + 1) * 128) = v1v;
    }
}

// ---------------------------------------------------------------------------
// K3: gather (unchanged). Warp = 2 queries; 4 channel-chunks of 32 via smem;
// y via REDUX.UMAX (z >= +0 post-ReLU => fp max == uint max).
// ---------------------------------------------------------------------------
__global__ __launch_bounds__(128) void gather_kernel(float* __restrict__ out)
{
    __shared__ float S[4][32 * 33];
    const int t = threadIdx.x, w = t >> 5, l = t & 31;
    const int Q0 = blockIdx.x * 8 + w * 2;
    const int qg = Q0 + (l >> 4);
    const int b = qg >> 11, i = qg & 2047, k = l & 15;
    const int i0 = Q0 & 2047;

    const int jl = g_idx[qg * 16 + k];
    const int gr = (b << 11) + jl;
    float* Sw = S[w];
    const unsigned gmask = (l < 16) ? 0x0000FFFFu : 0xFFFF0000u;

    for (int ch = 0; ch < 4; ch++) {
#pragma unroll 8
        for (int r = 0; r < 32; r++) {
            int row = __shfl_sync(0xffffffffu, gr, r);
            Sw[r * 33 + l] = g_z[(size_t)row * 128 + ch * 32 + l];
        }
        __syncwarp();
        float* ob = out + OUT_KNN + ((size_t)(b * 128 + ch * 32) * 2048 + i0) * 16 + l;
        float* yb = out + (size_t)(b * 128 + ch * 32) * 2048 + i;
#pragma unroll 8
        for (int oo = 0; oo < 32; oo++) {
            float v = Sw[l * 33 + oo];
            unsigned mv = __reduce_max_sync(gmask, __float_as_uint(v));
            ob[(size_t)oo * 32768] = v;
            if (k == 0) yb[oo * 2048] = __uint_as_float(mv);
        }
        __syncwarp();
    }
}

extern "C" void kernel_launch(void* const* d_in, const int* in_sizes, int n_in,
                              void* d_out, int out_size)
{
    const float* x      = (const float*)d_in[0];
    const float* coords = (const float*)d_in[1];
    const float* w1     = (const float*)d_in[2];
    const float* g1     = (const float*)d_in[3];
    const float* b1     = (const float*)d_in[4];
    const float* m1     = (const float*)d_in[5];
    const float* v1     = (const float*)d_in[6];
    const float* w2     = (const float*)d_in[7];
    const float* g2     = (const float*)d_in[8];
    const float* b2     = (const float*)d_in[9];
    const float* m2     = (const float*)d_in[10];
    const float* v2     = (const float*)d_in[11];
    float* out = (float*)d_out;

    // knn kept at launch index 3 (the slot ncu captures).
    transpose_kernel<<<64, 256>>>(w1, w2);
    layer1_kernel<<<512, 256>>>(x, g1, b1, m1, v1);
    layer2_kernel<<<512, 256>>>(g2, b2, m2, v2);
    knn_kernel<<<dim3(64, 8), 256>>>(coords, out);
    gather_kernel<<<2048, 128>>>(out);
}